// round 4
// baseline (speedup 1.0000x reference)
#include <cuda_runtime.h>
#include <math.h>

#define S_LEN  128
#define NBATCH 2048
#define HID    128
#define G4     512      // 4*HID
#define KTOT   256      // fused K = HID(x) + HID(h)
#define OUTDIM 128
#define NH     (NBATCH*HID)

#define SA_PITCH 68     // 64 + pad, 16B-aligned rows (68*4=272)
#define SW_PITCH 132    // 128 + pad, 16B-aligned rows (132*4=528)

#define STEP_SMEM ((256*SA_PITCH + 32*SW_PITCH)*4)   // 86528 B
#define PROJ_SMEM ((128*SA_PITCH + 32*SW_PITCH)*4)   // 51712 B

// ---------------- scratch (static device allocations; no cudaMalloc) ----------------
__device__ float g_hist[(size_t)S_LEN*NBATCH*HID];   // 134 MB: h_t history for projection
__device__ float g_h[2*NH];                          // ping-pong hidden state
__device__ float g_c[NH];                            // cell state (disjoint per CTA -> no race)
__device__ float g_Wp[G4*KTOT];                      // repacked [W_ih | W_hh], rows regrouped per h-block
__device__ float g_bp[G4];                           // b_ih + b_hh, same row order

// Repack weights: packed row = hb*128 + gate*32 + j  <->  orig row = gate*128 + hb*32 + j
// so CTA hb reads 128 contiguous rows covering all 4 gates for its 32 h-columns.
__global__ void pack_kernel(const float* __restrict__ W_ih, const float* __restrict__ W_hh,
                            const float* __restrict__ b_ih, const float* __restrict__ b_hh) {
    int idx = blockIdx.x*256 + threadIdx.x;          // 512 rows * 256 k
    int row = idx >> 8;
    int k   = idx & 255;
    int hb = row >> 7, rem = row & 127, gate = rem >> 5, j = rem & 31;
    int orow = gate*128 + hb*32 + j;
    float v = (k < HID) ? W_ih[orow*HID + k] : W_hh[orow*HID + (k - HID)];
    g_Wp[row*KTOT + k] = v;
    if (k == 0) g_bp[row] = b_ih[orow] + b_hh[orow];
}

__global__ void zero_kernel() {
    int idx = blockIdx.x*256 + threadIdx.x;
    if (idx < NH) { g_h[idx] = 0.0f; g_c[idx] = 0.0f; }
}

__device__ __forceinline__ float sigm(float v) { return 1.0f/(1.0f + __expf(-v)); }

// One timestep: gates[n,g] = b + [x_t, h_{s-1}] . Wcat[g,:]; then elementwise LSTM update.
// Grid: (32 n-blocks of 64) x (4 h-blocks of 32). 256 threads, 4x8 register tile.
__global__ void __launch_bounds__(256) lstm_step_kernel(const float* __restrict__ x, int s) {
    extern __shared__ float sm[];
    float* sA = sm;                      // [256][SA_PITCH]  k-major operand (x then h)
    float* sW = sm + 256*SA_PITCH;       // [32][SW_PITCH]   staged weight chunk, k-major

    const int tid = threadIdx.x;
    const int nb  = blockIdx.x;          // 0..31
    const int hb  = blockIdx.y;          // 0..3
    const int n0  = nb*64;

    const float* __restrict__ h_rd = g_h + (s & 1)*NH;
    float*       __restrict__ h_wr = g_h + ((s & 1) ^ 1)*NH;

    // Load A tile: sA[k][n_local]; k in [0,128) = x_t, [128,256) = h_{s-1}
    const float* xs = x + (size_t)s*NH;
    for (int e = tid; e < 64*128; e += 256) {
        int n_l = e >> 7;
        int h   = e & 127;
        size_t gi = (size_t)(n0 + n_l)*HID + h;
        sA[h*SA_PITCH + n_l]         = xs[gi];
        sA[(128 + h)*SA_PITCH + n_l] = h_rd[gi];
    }

    const int tx = tid & 15;             // sample group  -> samples tx*4..tx*4+3
    const int ty = tid >> 4;             // gate-row group-> rows ty*8..ty*8+7

    float acc[4][8];
    #pragma unroll
    for (int q = 0; q < 8; q++) {
        float b = g_bp[hb*128 + ty*8 + q];
        #pragma unroll
        for (int i = 0; i < 4; i++) acc[i][q] = b;
    }
    __syncthreads();

    const float* Wbase = g_Wp + (size_t)hb*128*KTOT;
    for (int kc = 0; kc < KTOT; kc += 32) {
        // stage 128 rows x 32 k into sW[k][row]
        #pragma unroll
        for (int rep = 0; rep < 16; rep++) {
            int e = tid + rep*256;
            int r = e >> 5, kk = e & 31;
            sW[kk*SW_PITCH + r] = Wbase[r*KTOT + kc + kk];
        }
        __syncthreads();
        #pragma unroll
        for (int kk = 0; kk < 32; kk++) {
            const float4 a  = *(const float4*)&sA[(kc + kk)*SA_PITCH + tx*4];
            const float4 w0 = *(const float4*)&sW[kk*SW_PITCH + ty*8];
            const float4 w1 = *(const float4*)&sW[kk*SW_PITCH + ty*8 + 4];
            float av[4] = {a.x, a.y, a.z, a.w};
            float wv[8] = {w0.x, w0.y, w0.z, w0.w, w1.x, w1.y, w1.z, w1.w};
            #pragma unroll
            for (int i = 0; i < 4; i++)
                #pragma unroll
                for (int q = 0; q < 8; q++)
                    acc[i][q] = fmaf(av[i], wv[q], acc[i][q]);
        }
        __syncthreads();
    }

    // Park gates in smem (reuse sA rows 0..127) for cross-thread i/f/g/o gather
    #pragma unroll
    for (int q = 0; q < 8; q++) {
        int r = ty*8 + q;
        #pragma unroll
        for (int i = 0; i < 4; i++)
            sA[r*SA_PITCH + tx*4 + i] = acc[i][q];
    }
    __syncthreads();

    float* hist_s = g_hist + (size_t)s*NH;
    for (int e = tid; e < 2048; e += 256) {
        int n_l = e & 63;
        int j   = e >> 6;                         // 0..31 h within block
        float iv = sigm (sA[(      j)*SA_PITCH + n_l]);
        float fv = sigm (sA[( 32 + j)*SA_PITCH + n_l]);
        float gv = tanhf(sA[( 64 + j)*SA_PITCH + n_l]);
        float ov = sigm (sA[( 96 + j)*SA_PITCH + n_l]);
        size_t addr = (size_t)(n0 + n_l)*HID + hb*32 + j;
        float c = fv*g_c[addr] + iv*gv;
        float h = ov*tanhf(c);
        g_c[addr]    = c;
        h_wr[addr]   = h;
        hist_s[addr] = h;
    }
}

// Projection: pred[m, o] = hist[m, :] . W_out[o, :] + b_out[o], m = s*N + n (flat 262144 rows)
__global__ void __launch_bounds__(256) proj_kernel(const float* __restrict__ W_out,
                                                   const float* __restrict__ b_out,
                                                   float* __restrict__ out) {
    extern __shared__ float sm[];
    float* sA = sm;                      // [128][SA_PITCH]
    float* sW = sm + 128*SA_PITCH;       // [32][SW_PITCH]

    const int tid = threadIdx.x;
    const int m0  = blockIdx.x*64;

    for (int e = tid; e < 64*128; e += 256) {
        int r_l = e >> 7;
        int h   = e & 127;
        sA[h*SA_PITCH + r_l] = g_hist[(size_t)(m0 + r_l)*HID + h];
    }

    const int tx = tid & 15;
    const int ty = tid >> 4;

    float acc[4][8];
    #pragma unroll
    for (int q = 0; q < 8; q++) {
        float b = b_out[ty*8 + q];
        #pragma unroll
        for (int i = 0; i < 4; i++) acc[i][q] = b;
    }
    __syncthreads();

    for (int kc = 0; kc < HID; kc += 32) {
        #pragma unroll
        for (int rep = 0; rep < 16; rep++) {
            int e = tid + rep*256;
            int o = e >> 5, kk = e & 31;
            sW[kk*SW_PITCH + o] = W_out[o*HID + kc + kk];
        }
        __syncthreads();
        #pragma unroll
        for (int kk = 0; kk < 32; kk++) {
            const float4 a  = *(const float4*)&sA[(kc + kk)*SA_PITCH + tx*4];
            const float4 w0 = *(const float4*)&sW[kk*SW_PITCH + ty*8];
            const float4 w1 = *(const float4*)&sW[kk*SW_PITCH + ty*8 + 4];
            float av[4] = {a.x, a.y, a.z, a.w};
            float wv[8] = {w0.x, w0.y, w0.z, w0.w, w1.x, w1.y, w1.z, w1.w};
            #pragma unroll
            for (int i = 0; i < 4; i++)
                #pragma unroll
                for (int q = 0; q < 8; q++)
                    acc[i][q] = fmaf(av[i], wv[q], acc[i][q]);
        }
        __syncthreads();
    }

    #pragma unroll
    for (int i = 0; i < 4; i++) {
        size_t base = (size_t)(m0 + tx*4 + i)*OUTDIM + ty*8;
        float4 v0 = make_float4(acc[i][0], acc[i][1], acc[i][2], acc[i][3]);
        float4 v1 = make_float4(acc[i][4], acc[i][5], acc[i][6], acc[i][7]);
        *(float4*)&out[base]     = v0;
        *(float4*)&out[base + 4] = v1;
    }
}

extern "C" void kernel_launch(void* const* d_in, const int* in_sizes, int n_in,
                              void* d_out, int out_size) {
    const float* x     = (const float*)d_in[0];
    const float* W_ih  = (const float*)d_in[1];
    const float* W_hh  = (const float*)d_in[2];
    const float* b_ih  = (const float*)d_in[3];
    const float* b_hh  = (const float*)d_in[4];
    const float* W_out = (const float*)d_in[5];
    const float* b_out = (const float*)d_in[6];
    float* out = (float*)d_out;
    (void)in_sizes; (void)n_in; (void)out_size;

    cudaFuncSetAttribute(lstm_step_kernel, cudaFuncAttributeMaxDynamicSharedMemorySize, STEP_SMEM);
    cudaFuncSetAttribute(proj_kernel,      cudaFuncAttributeMaxDynamicSharedMemorySize, PROJ_SMEM);

    pack_kernel<<<512, 256>>>(W_ih, W_hh, b_ih, b_hh);
    zero_kernel<<<1024, 256>>>();

    for (int s = 0; s < S_LEN; s++)
        lstm_step_kernel<<<dim3(32, 4), 256, STEP_SMEM>>>(x, s);

    proj_kernel<<<4096, 256, PROJ_SMEM>>>(W_out, b_out, out);
}